// round 7
// baseline (speedup 1.0000x reference)
#include <cuda_runtime.h>
#include <math.h>

// Problem constants (match reference)
#define BATCH 4
#define NPTS  300000
#define NX_   540
#define NY_   540
#define NZ_   8
#define NV_   (NX_ * NY_ * NZ_)          // 2,332,800
#define NFEAT 5

// Output layout (tuple flattened, all float32):
//   [0, BATCH*NV_*NFEAT)   voxel means (46,656,000)
//   [.., +BATCH*NV_)       counts       (9,331,200)
//   last 3                 shape {540, 540, 8}

#define SUMS_B   (NV_ * NFEAT)           // 11,664,000 floats per batch
#define SUMS_B4  (SUMS_B / 4)            //  2,916,000 float4
#define CNTS_B4  (NV_ / 4)               //    583,200 float4
#define ZERO_B4  (SUMS_B4 + CNTS_B4)     //  3,499,200 float4 per batch

#define THREADS      256
#define SCAT_GROUPS  (NPTS / 4)                                   // 75,000
#define SCAT_BLOCKS  ((SCAT_GROUPS + THREADS - 1) / THREADS)      // 293
#define FIN_BLOCKS   ((CNTS_B4 + THREADS - 1) / THREADS)          // 2,279
#define ZERO_BLOCKS  ((ZERO_B4 + THREADS * 4 - 1) / (THREADS * 4))// 3,418

// Role-interleave tile: every 21 consecutive block IDs contain
// 1 scatter, 8 fin, 12 zero blocks, so every scheduling wave carries a
// proportional mix of all three roles (scatter: atomic path; fin: L2 read;
// zero: L2 write) and they genuinely overlap.
#define TILE          21
#define TILE_FIN      8
#define TILE_ZERO     12
#define N_TILES       SCAT_BLOCKS                     // 293
// capacity check: 293*8 = 2344 >= 2279, 293*12 = 3516 >= 3418
#define GRID_FULL     (N_TILES * TILE)                // 6,153

// ---------------------------------------------------------------------------
__device__ __forceinline__ void red_add_v2(float* addr, float a, float b) {
    asm volatile("red.global.add.v2.f32 [%0], {%1, %2};"
                 :: "l"(addr), "f"(a), "f"(b) : "memory");
}
__device__ __forceinline__ void red_add(float* addr, float a) {
    asm volatile("red.global.add.f32 [%0], %1;"
                 :: "l"(addr), "f"(a) : "memory");
}

// ---------------------------------------------------------------------------
__device__ __forceinline__ void scatter_point(float x, float y, float z,
                                              float f3, float f4,
                                              float* __restrict__ sums,
                                              float* __restrict__ cnts) {
    // keep = all(xyz >= LO) & all(xyz <= HI), inclusive both sides
    bool keep = (x >= -54.0f) & (x <= 54.0f) &
                (y >= -54.0f) & (y <= 54.0f) &
                (z >= -5.0f)  & (z <= 3.0f);
    if (!keep) return;

    // Reference (XLA) folds /VOX into multiply by the rounded reciprocal:
    // 1/0.2f -> exactly 5.0f. Kept points have non-negative operands, so
    // truncation == floor.
    int cx = (int)((x + 54.0f) * 5.0f);
    int cy = (int)((y + 54.0f) * 5.0f);
    int cz = (int)(z + 5.0f);
    cx = min(max(cx, 0), NX_ - 1);
    cy = min(max(cy, 0), NY_ - 1);
    cz = min(max(cz, 0), NZ_ - 1);

    unsigned lin = ((unsigned)cz * NY_ + (unsigned)cy) * NX_ + (unsigned)cx;

    float* s = sums + (size_t)lin * NFEAT;
    if ((lin & 1) == 0) {
        red_add_v2(s + 0, x, y);
        red_add_v2(s + 2, z, f3);
        red_add(s + 4, f4);
    } else {
        red_add(s + 0, x);
        red_add_v2(s + 1, y, z);
        red_add_v2(s + 3, f3, f4);
    }
    red_add(cnts + lin, 1.0f);
}

// ---------------------------------------------------------------------------
// Fused pipeline stage with wave-interleaved roles, each on a DIFFERENT batch:
//   scatter(b)   — LTS atomic path
//   finalize(b-1)— L2 read + sparse RMW
//   zero(b+1)    — L2 write / lazy DRAM writeback
__global__ void __launch_bounds__(THREADS)
mega_kernel(const float4* __restrict__ scat_pts,
            float* __restrict__ scat_sums, float* __restrict__ scat_cnts,
            int has_scat,
            float* __restrict__ fin_sums, const float4* __restrict__ fin_cnts4,
            int has_fin,
            float4* __restrict__ zero_sums4, float4* __restrict__ zero_cnts4,
            int has_zero,
            float* __restrict__ shape_tail) {
    unsigned tile = blockIdx.x / TILE;
    unsigned slot = blockIdx.x % TILE;

    if (slot == 0) {
        // ---- scatter role ----
        if (!has_scat) return;
        unsigned rb = tile;                       // role block id [0, SCAT_BLOCKS)
        unsigned t = rb * THREADS + threadIdx.x;
        if (t >= SCAT_GROUPS) return;
        const float4* p = scat_pts + (size_t)t * 5;
        float4 q0 = p[0];
        float4 q1 = p[1];
        float4 q2 = p[2];
        float4 q3 = p[3];
        float4 q4 = p[4];
        scatter_point(q0.x, q0.y, q0.z, q0.w, q1.x, scat_sums, scat_cnts);
        scatter_point(q1.y, q1.z, q1.w, q2.x, q2.y, scat_sums, scat_cnts);
        scatter_point(q2.z, q2.w, q3.x, q3.y, q3.z, scat_sums, scat_cnts);
        scatter_point(q3.w, q4.x, q4.y, q4.z, q4.w, scat_sums, scat_cnts);
    } else if (slot <= TILE_FIN) {
        // ---- finalize role: only cnt>=2 voxels need the divide ----
        if (!has_fin) return;
        unsigned rb = tile * TILE_FIN + (slot - 1);
        if (rb >= FIN_BLOCKS) return;
        unsigned i = rb * THREADS + threadIdx.x;
        if (i >= CNTS_B4) return;
        float4 c = fin_cnts4[i];
        size_t v0 = (size_t)i * 4;
        float cs[4] = {c.x, c.y, c.z, c.w};
        #pragma unroll
        for (int k = 0; k < 4; k++) {
            if (cs[k] > 1.5f) {
                float* s = fin_sums + (v0 + k) * NFEAT;
                #pragma unroll
                for (int f = 0; f < NFEAT; f++)
                    s[f] = __fdiv_rn(s[f], cs[k]);
            }
        }
    } else {
        // ---- zero role: 4 float4 per thread across sums then counts ----
        if (!has_zero) return;
        unsigned rb = tile * TILE_ZERO + (slot - 1 - TILE_FIN);
        if (rb >= ZERO_BLOCKS) return;
        unsigned base = rb * (THREADS * 4) + threadIdx.x;
        const float4 z4 = make_float4(0.f, 0.f, 0.f, 0.f);
        #pragma unroll
        for (int k = 0; k < 4; k++) {
            unsigned i = base + k * THREADS;
            if (i < SUMS_B4) {
                zero_sums4[i] = z4;
            } else if (i < ZERO_B4) {
                zero_cnts4[i - SUMS_B4] = z4;
            }
        }
        if (shape_tail != nullptr && base == 0) {
            shape_tail[0] = 540.0f;
            shape_tail[1] = 540.0f;
            shape_tail[2] = 8.0f;
        }
    }
}

// ---------------------------------------------------------------------------
extern "C" void kernel_launch(void* const* d_in, const int* in_sizes, int n_in,
                              void* d_out, int out_size) {
    const float* pts = (const float*)d_in[0];
    float* out = (float*)d_out;

    const size_t n_sums = (size_t)BATCH * SUMS_B;        // 46,656,000
    float* sums_base = out;
    float* cnts_base = out + n_sums;
    float* shape_tail = out + n_sums + (size_t)BATCH * NV_;

    auto sums_b = [&](int b) { return sums_base + (size_t)b * SUMS_B; };
    auto cnts_b = [&](int b) { return cnts_base + (size_t)b * NV_; };
    auto pts_b  = [&](int b) {
        return (const float4*)(pts + (size_t)b * NPTS * NFEAT);
    };

    // Software pipeline: stage s runs scatter(s), finalize(s-1), zero(s+1).
    for (int s = -1; s <= 4; s++) {
        int b_scat = s;
        int b_fin  = s - 1;
        int b_zero = s + 1;

        int has_scat = (b_scat >= 0 && b_scat < BATCH);
        int has_fin  = (b_fin  >= 0 && b_fin  < BATCH);
        int has_zero = (b_zero >= 0 && b_zero < BATCH);
        if (!has_scat && !has_fin && !has_zero) continue;

        mega_kernel<<<GRID_FULL, THREADS>>>(
            has_scat ? pts_b(b_scat) : nullptr,
            has_scat ? sums_b(b_scat) : nullptr,
            has_scat ? cnts_b(b_scat) : nullptr,
            has_scat,
            has_fin ? sums_b(b_fin) : nullptr,
            has_fin ? (const float4*)cnts_b(b_fin) : nullptr,
            has_fin,
            has_zero ? (float4*)sums_b(b_zero) : nullptr,
            has_zero ? (float4*)cnts_b(b_zero) : nullptr,
            has_zero,
            (b_zero == 0) ? shape_tail : nullptr);
    }
}

// round 8
// speedup vs baseline: 1.1347x; 1.1347x over previous
#include <cuda_runtime.h>
#include <math.h>

// Problem constants (match reference)
#define BATCH 4
#define NPTS  300000
#define NX_   540
#define NY_   540
#define NZ_   8
#define NV_   (NX_ * NY_ * NZ_)          // 2,332,800
#define NFEAT 5

// d_out layout (tuple flattened, all float32):
//   [0, BATCH*NV_*NFEAT)   voxel means (46,656,000)
//   [.., +BATCH*NV_)       counts       (9,331,200)
//   last 3                 shape {540, 540, 8}
#define SUMS_B   (NV_ * NFEAT)           // 11,664,000 floats per batch

// Scratch: 24B record per voxel [x, y, z, f3, f4, cnt]; two buffers so
// scatter(b) and finalize(b-1) pipeline. Each 56 MB; both fit in 126 MB L2.
// Zeroed at module load; finalize restores zeros to every dirtied record
// (dirty <=> cnt > 0), keeping the all-zeros invariant across graph replays.
#define REC 6
__device__ __align__(16) float g_scratch[2][(size_t)NV_ * REC];

#define THREADS      256
#define SCAT_GROUPS  (NPTS / 4)                                   // 75,000
#define SCAT_BLOCKS  ((SCAT_GROUPS + THREADS - 1) / THREADS)      // 293
#define FIN_GROUPS   (NV_ / 4)                                    // 583,200
#define FIN_BLOCKS   ((FIN_GROUPS + THREADS - 1) / THREADS)       // 2,279

// ---------------------------------------------------------------------------
__device__ __forceinline__ void red_add_v2(float* addr, float a, float b) {
    asm volatile("red.global.add.v2.f32 [%0], {%1, %2};"
                 :: "l"(addr), "f"(a), "f"(b) : "memory");
}
__device__ __forceinline__ void red_add_v4(float* addr, float a, float b,
                                           float c, float d) {
    asm volatile("red.global.add.v4.f32 [%0], {%1, %2, %3, %4};"
                 :: "l"(addr), "f"(a), "f"(b), "f"(c), "f"(d) : "memory");
}

// ---------------------------------------------------------------------------
__device__ __forceinline__ void scatter_point(float x, float y, float z,
                                              float f3, float f4,
                                              float* __restrict__ scratch) {
    // keep = all(xyz >= LO) & all(xyz <= HI), inclusive both sides
    bool keep = (x >= -54.0f) & (x <= 54.0f) &
                (y >= -54.0f) & (y <= 54.0f) &
                (z >= -5.0f)  & (z <= 3.0f);
    if (!keep) return;

    // Reference (XLA) folds /VOX into multiply by the rounded reciprocal:
    // 1/0.2f -> exactly 5.0f. Kept points have non-negative operands, so
    // truncation == floor. (Bit-exact vs reference — do not change.)
    int cx = (int)((x + 54.0f) * 5.0f);
    int cy = (int)((y + 54.0f) * 5.0f);
    int cz = (int)(z + 5.0f);
    cx = min(max(cx, 0), NX_ - 1);
    cy = min(max(cy, 0), NY_ - 1);
    cz = min(max(cz, 0), NZ_ - 1);

    unsigned lin = ((unsigned)cz * NY_ + (unsigned)cy) * NX_ + (unsigned)cx;

    // Record at byte offset 24*lin. lin even -> 16B-aligned start;
    // lin odd -> start ≡ 8 (mod 16), so r+2 is 16B-aligned.
    float* r = scratch + (size_t)lin * REC;
    if ((lin & 1) == 0) {
        red_add_v4(r + 0, x, y, z, f3);
        red_add_v2(r + 4, f4, 1.0f);
    } else {
        red_add_v2(r + 0, x, y);
        red_add_v4(r + 2, z, f3, f4, 1.0f);
    }
}

// ---------------------------------------------------------------------------
// Fused pipeline stage: contiguous block ranges (scatter first).
//   scatter(b)   -> g_scratch[b & 1]    (REDG path, L2-resident)
//   finalize(b-1)-> reads g_scratch[(b-1)&1], streams dense means+counts to
//                   d_out (__stcs), restores zeros to dirtied scratch.
__global__ void __launch_bounds__(THREADS)
mega_kernel(const float4* __restrict__ scat_pts, int scat_buf,
            unsigned n_scat,
            int fin_buf, float* __restrict__ fin_out_sums,
            float* __restrict__ fin_out_cnts,
            float* __restrict__ shape_tail) {
    unsigned bid = blockIdx.x;

    if (bid < n_scat) {
        // ---- scatter: 4 consecutive points = 5 float4 loads ----
        float* scratch = g_scratch[scat_buf];
        unsigned t = bid * THREADS + threadIdx.x;
        if (shape_tail != nullptr && t == 0) {
            shape_tail[0] = 540.0f;
            shape_tail[1] = 540.0f;
            shape_tail[2] = 8.0f;
        }
        if (t >= SCAT_GROUPS) return;
        const float4* p = scat_pts + (size_t)t * 5;
        float4 q0 = __ldcs(p + 0);
        float4 q1 = __ldcs(p + 1);
        float4 q2 = __ldcs(p + 2);
        float4 q3 = __ldcs(p + 3);
        float4 q4 = __ldcs(p + 4);
        scatter_point(q0.x, q0.y, q0.z, q0.w, q1.x, scratch);
        scatter_point(q1.y, q1.z, q1.w, q2.x, q2.y, scratch);
        scatter_point(q2.z, q2.w, q3.x, q3.y, q3.z, scratch);
        scatter_point(q3.w, q4.x, q4.y, q4.z, q4.w, scratch);
        return;
    }
    bid -= n_scat;

    // ---- finalize: 4 voxels per thread = 6 float4 scratch reads ----
    unsigned g = bid * THREADS + threadIdx.x;
    if (g >= FIN_GROUPS) return;

    float4* sr = (float4*)(g_scratch[fin_buf] + (size_t)g * 4 * REC);
    float4 q0 = sr[0], q1 = sr[1], q2 = sr[2],
           q3 = sr[3], q4 = sr[4], q5 = sr[5];

    // voxel k floats: [6k .. 6k+6) = [x,y,z,f3,f4,cnt]
    float c0 = q1.y, c1 = q2.w, c2 = q4.y, c3 = q5.w;

    float v0x = q0.x, v0y = q0.y, v0z = q0.z, v0a = q0.w, v0b = q1.x;
    float v1x = q1.z, v1y = q1.w, v1z = q2.x, v1a = q2.y, v1b = q2.z;
    float v2x = q3.x, v2y = q3.y, v2z = q3.z, v2a = q3.w, v2b = q4.x;
    float v3x = q4.z, v3y = q4.w, v3z = q5.x, v3a = q5.y, v3b = q5.z;

    // mean = sum / max(cnt, 1); cnt<=1 cases are already exact passthrough.
    if (c0 > 1.5f) { v0x = __fdiv_rn(v0x, c0); v0y = __fdiv_rn(v0y, c0);
                     v0z = __fdiv_rn(v0z, c0); v0a = __fdiv_rn(v0a, c0);
                     v0b = __fdiv_rn(v0b, c0); }
    if (c1 > 1.5f) { v1x = __fdiv_rn(v1x, c1); v1y = __fdiv_rn(v1y, c1);
                     v1z = __fdiv_rn(v1z, c1); v1a = __fdiv_rn(v1a, c1);
                     v1b = __fdiv_rn(v1b, c1); }
    if (c2 > 1.5f) { v2x = __fdiv_rn(v2x, c2); v2y = __fdiv_rn(v2y, c2);
                     v2z = __fdiv_rn(v2z, c2); v2a = __fdiv_rn(v2a, c2);
                     v2b = __fdiv_rn(v2b, c2); }
    if (c3 > 1.5f) { v3x = __fdiv_rn(v3x, c3); v3y = __fdiv_rn(v3y, c3);
                     v3z = __fdiv_rn(v3z, c3); v3a = __fdiv_rn(v3a, c3);
                     v3b = __fdiv_rn(v3b, c3); }

    // Dense streaming writes to d_out (bypass L2 residency with .cs):
    // 4 voxels x 5 floats = 5 float4, plus 1 float4 of counts.
    float4* outs = (float4*)(fin_out_sums + (size_t)g * 20);
    __stcs(outs + 0, make_float4(v0x, v0y, v0z, v0a));
    __stcs(outs + 1, make_float4(v0b, v1x, v1y, v1z));
    __stcs(outs + 2, make_float4(v1a, v1b, v2x, v2y));
    __stcs(outs + 3, make_float4(v2z, v2a, v2b, v3x));
    __stcs(outs + 4, make_float4(v3y, v3z, v3a, v3b));
    __stcs((float4*)(fin_out_cnts + (size_t)g * 4),
           make_float4(c0, c1, c2, c3));

    // Restore zeros to dirtied scratch (dirty <=> cnt > 0). Pair granularity:
    // voxels {0,1} live in q0..q2, voxels {2,3} in q3..q5.
    const float4 z4 = make_float4(0.f, 0.f, 0.f, 0.f);
    if (c0 > 0.5f || c1 > 0.5f) { sr[0] = z4; sr[1] = z4; sr[2] = z4; }
    if (c2 > 0.5f || c3 > 0.5f) { sr[3] = z4; sr[4] = z4; sr[5] = z4; }
}

// ---------------------------------------------------------------------------
extern "C" void kernel_launch(void* const* d_in, const int* in_sizes, int n_in,
                              void* d_out, int out_size) {
    const float* pts = (const float*)d_in[0];
    float* out = (float*)d_out;

    const size_t n_sums = (size_t)BATCH * SUMS_B;        // 46,656,000
    float* sums_base = out;
    float* cnts_base = out + n_sums;
    float* shape_tail = out + n_sums + (size_t)BATCH * NV_;

    // Pipeline: stage s runs scatter(b=s) and finalize(b=s-1).
    for (int s = 0; s <= BATCH; s++) {
        int b_scat = s;
        int b_fin  = s - 1;
        bool has_scat = (b_scat < BATCH);
        bool has_fin  = (b_fin >= 0);

        unsigned n_scat = has_scat ? SCAT_BLOCKS : 0;
        unsigned n_fin  = has_fin  ? FIN_BLOCKS  : 0;

        mega_kernel<<<n_scat + n_fin, THREADS>>>(
            has_scat ? (const float4*)(pts + (size_t)b_scat * NPTS * NFEAT)
                     : nullptr,
            has_scat ? (b_scat & 1) : 0,
            n_scat,
            has_fin ? (b_fin & 1) : 0,
            has_fin ? (sums_base + (size_t)b_fin * SUMS_B) : nullptr,
            has_fin ? (cnts_base + (size_t)b_fin * NV_) : nullptr,
            (s == 0) ? shape_tail : nullptr);
    }
}

// round 9
// speedup vs baseline: 1.1943x; 1.0525x over previous
#include <cuda_runtime.h>
#include <math.h>

// Problem constants (match reference)
#define BATCH 4
#define NPTS  300000
#define NX_   540
#define NY_   540
#define NZ_   8
#define NV_   (NX_ * NY_ * NZ_)          // 2,332,800
#define NFEAT 5

// d_out layout (tuple flattened, all float32):
//   [0, BATCH*NV_*NFEAT)   voxel means (46,656,000)
//   [.., +BATCH*NV_)       counts       (9,331,200)
//   last 3                 shape {540, 540, 8}
#define SUMS_B   (NV_ * NFEAT)           // 11,664,000 floats per batch

// z-split halves: lin is z-major, so z in [0,4) and [4,8) are contiguous
// ranges of NV_half voxels each.
#define NZ_H     (NZ_ / 2)               // 4
#define NV_H     (NX_ * NY_ * NZ_H)      // 1,166,400 voxels per half

// Scratch: 24 B record [x,y,z,f3,f4,cnt] per voxel, HALF-batch sized.
// Two buffers of 28 MB => 56 MB live in L2, comfortably resident.
// Zeroed at load; finalize restores zeros to dirtied records (dirty <=> cnt>0),
// keeping the all-zeros invariant across stages and graph replays.
#define REC 6
__device__ __align__(16) float g_scratch[2][(size_t)NV_H * REC];

#define THREADS       256
#define SCAT_GROUPS   (NPTS / 4)                                  // 75,000
#define SCAT_BLOCKS   ((SCAT_GROUPS + THREADS - 1) / THREADS)     // 293
#define FIN_GROUPS    (NV_H / 4)                                  // 291,600
#define FIN_BLOCKS    ((FIN_GROUPS + THREADS - 1) / THREADS)      // 1,140

// ---------------------------------------------------------------------------
__device__ __forceinline__ void red_add_v2(float* addr, float a, float b) {
    asm volatile("red.global.add.v2.f32 [%0], {%1, %2};"
                 :: "l"(addr), "f"(a), "f"(b) : "memory");
}
__device__ __forceinline__ void red_add_v4(float* addr, float a, float b,
                                           float c, float d) {
    asm volatile("red.global.add.v4.f32 [%0], {%1, %2, %3, %4};"
                 :: "l"(addr), "f"(a), "f"(b), "f"(c), "f"(d) : "memory");
}

// ---------------------------------------------------------------------------
__device__ __forceinline__ void scatter_point(float x, float y, float z,
                                              float f3, float f4,
                                              float* __restrict__ scratch,
                                              int z0) {
    // keep = all(xyz >= LO) & all(xyz <= HI), inclusive both sides
    bool keep = (x >= -54.0f) & (x <= 54.0f) &
                (y >= -54.0f) & (y <= 54.0f) &
                (z >= -5.0f)  & (z <= 3.0f);
    if (!keep) return;

    // Reference (XLA) folds /VOX into multiply by the rounded reciprocal:
    // 1/0.2f -> exactly 5.0f. Kept points have non-negative operands, so
    // truncation == floor. (Bit-exact vs reference — do not change.)
    int cz = (int)(z + 5.0f);
    cz = min(max(cz, 0), NZ_ - 1);
    if (cz < z0 || cz >= z0 + NZ_H) return;   // other half handles it

    int cx = (int)((x + 54.0f) * 5.0f);
    int cy = (int)((y + 54.0f) * 5.0f);
    cx = min(max(cx, 0), NX_ - 1);
    cy = min(max(cy, 0), NY_ - 1);

    unsigned lin = ((unsigned)(cz - z0) * NY_ + (unsigned)cy) * NX_
                 + (unsigned)cx;

    // Record at byte offset 24*lin: lin even -> 16B-aligned; lin odd -> r+2
    // is 16B-aligned.
    float* r = scratch + (size_t)lin * REC;
    if ((lin & 1) == 0) {
        red_add_v4(r + 0, x, y, z, f3);
        red_add_v2(r + 4, f4, 1.0f);
    } else {
        red_add_v2(r + 0, x, y);
        red_add_v4(r + 2, z, f3, f4, 1.0f);
    }
}

// ---------------------------------------------------------------------------
// Fused pipeline stage, contiguous block ranges (scatter first):
//   scatter(half g)    -> g_scratch[g & 1]   (REDG path, L2-resident)
//   finalize(half g-1) -> reads g_scratch[(g-1)&1], streams dense
//                         means+counts to d_out (.cs), restores zeros.
__global__ void __launch_bounds__(THREADS)
mega_kernel(const float4* __restrict__ scat_pts, int scat_buf, int scat_z0,
            unsigned n_scat,
            int fin_buf, float* __restrict__ fin_out_sums,
            float* __restrict__ fin_out_cnts,
            float* __restrict__ shape_tail) {
    unsigned bid = blockIdx.x;

    if (bid < n_scat) {
        // ---- scatter: 4 consecutive points = 5 float4 loads ----
        float* scratch = g_scratch[scat_buf];
        unsigned t = bid * THREADS + threadIdx.x;
        if (shape_tail != nullptr && t == 0) {
            shape_tail[0] = 540.0f;
            shape_tail[1] = 540.0f;
            shape_tail[2] = 8.0f;
        }
        if (t >= SCAT_GROUPS) return;
        const float4* p = scat_pts + (size_t)t * 5;
        float4 q0 = __ldcs(p + 0);
        float4 q1 = __ldcs(p + 1);
        float4 q2 = __ldcs(p + 2);
        float4 q3 = __ldcs(p + 3);
        float4 q4 = __ldcs(p + 4);
        scatter_point(q0.x, q0.y, q0.z, q0.w, q1.x, scratch, scat_z0);
        scatter_point(q1.y, q1.z, q1.w, q2.x, q2.y, scratch, scat_z0);
        scatter_point(q2.z, q2.w, q3.x, q3.y, q3.z, scratch, scat_z0);
        scatter_point(q3.w, q4.x, q4.y, q4.z, q4.w, scratch, scat_z0);
        return;
    }
    bid -= n_scat;

    // ---- finalize: 4 voxels per thread = 6 float4 scratch reads ----
    unsigned g = bid * THREADS + threadIdx.x;
    if (g >= FIN_GROUPS) return;

    float4* sr = (float4*)(g_scratch[fin_buf] + (size_t)g * 4 * REC);
    float4 q0 = sr[0], q1 = sr[1], q2 = sr[2],
           q3 = sr[3], q4 = sr[4], q5 = sr[5];

    // voxel k floats: [6k .. 6k+6) = [x,y,z,f3,f4,cnt]
    float c0 = q1.y, c1 = q2.w, c2 = q4.y, c3 = q5.w;

    float v0x = q0.x, v0y = q0.y, v0z = q0.z, v0a = q0.w, v0b = q1.x;
    float v1x = q1.z, v1y = q1.w, v1z = q2.x, v1a = q2.y, v1b = q2.z;
    float v2x = q3.x, v2y = q3.y, v2z = q3.z, v2a = q3.w, v2b = q4.x;
    float v3x = q4.z, v3y = q4.w, v3z = q5.x, v3a = q5.y, v3b = q5.z;

    // mean = sum / max(cnt, 1); cnt<=1 cases are already exact passthrough.
    if (c0 > 1.5f) { v0x = __fdiv_rn(v0x, c0); v0y = __fdiv_rn(v0y, c0);
                     v0z = __fdiv_rn(v0z, c0); v0a = __fdiv_rn(v0a, c0);
                     v0b = __fdiv_rn(v0b, c0); }
    if (c1 > 1.5f) { v1x = __fdiv_rn(v1x, c1); v1y = __fdiv_rn(v1y, c1);
                     v1z = __fdiv_rn(v1z, c1); v1a = __fdiv_rn(v1a, c1);
                     v1b = __fdiv_rn(v1b, c1); }
    if (c2 > 1.5f) { v2x = __fdiv_rn(v2x, c2); v2y = __fdiv_rn(v2y, c2);
                     v2z = __fdiv_rn(v2z, c2); v2a = __fdiv_rn(v2a, c2);
                     v2b = __fdiv_rn(v2b, c2); }
    if (c3 > 1.5f) { v3x = __fdiv_rn(v3x, c3); v3y = __fdiv_rn(v3y, c3);
                     v3z = __fdiv_rn(v3z, c3); v3a = __fdiv_rn(v3a, c3);
                     v3b = __fdiv_rn(v3b, c3); }

    // Dense streaming writes to d_out (.cs keeps them out of L2 residency):
    float4* outs = (float4*)(fin_out_sums + (size_t)g * 20);
    __stcs(outs + 0, make_float4(v0x, v0y, v0z, v0a));
    __stcs(outs + 1, make_float4(v0b, v1x, v1y, v1z));
    __stcs(outs + 2, make_float4(v1a, v1b, v2x, v2y));
    __stcs(outs + 3, make_float4(v2z, v2a, v2b, v3x));
    __stcs(outs + 4, make_float4(v3y, v3z, v3a, v3b));
    __stcs((float4*)(fin_out_cnts + (size_t)g * 4),
           make_float4(c0, c1, c2, c3));

    // Restore zeros to dirtied scratch (dirty <=> cnt > 0). Pair granularity:
    // voxels {0,1} live in q0..q2, voxels {2,3} in q3..q5.
    const float4 z4 = make_float4(0.f, 0.f, 0.f, 0.f);
    if (c0 > 0.5f || c1 > 0.5f) { sr[0] = z4; sr[1] = z4; sr[2] = z4; }
    if (c2 > 0.5f || c3 > 0.5f) { sr[3] = z4; sr[4] = z4; sr[5] = z4; }
}

// ---------------------------------------------------------------------------
extern "C" void kernel_launch(void* const* d_in, const int* in_sizes, int n_in,
                              void* d_out, int out_size) {
    const float* pts = (const float*)d_in[0];
    float* out = (float*)d_out;

    const size_t n_sums = (size_t)BATCH * SUMS_B;        // 46,656,000
    float* sums_base = out;
    float* cnts_base = out + n_sums;
    float* shape_tail = out + n_sums + (size_t)BATCH * NV_;

    const int NHALF = BATCH * 2;   // 8 half-batches, index g = b*2 + hz

    // Pipeline: stage s runs scatter(half s) and finalize(half s-1).
    for (int s = 0; s <= NHALF; s++) {
        int g_scat = s;
        int g_fin  = s - 1;
        bool has_scat = (g_scat < NHALF);
        bool has_fin  = (g_fin >= 0);

        unsigned n_scat = has_scat ? SCAT_BLOCKS : 0;
        unsigned n_fin  = has_fin  ? FIN_BLOCKS  : 0;

        int b_scat = g_scat / 2, hz_scat = g_scat % 2;
        int b_fin  = g_fin  / 2, hz_fin  = g_fin  % 2;

        mega_kernel<<<n_scat + n_fin, THREADS>>>(
            has_scat ? (const float4*)(pts + (size_t)b_scat * NPTS * NFEAT)
                     : nullptr,
            has_scat ? (g_scat & 1) : 0,
            hz_scat * NZ_H,
            n_scat,
            has_fin ? (g_fin & 1) : 0,
            has_fin ? (sums_base + (size_t)b_fin * SUMS_B
                       + (size_t)hz_fin * NV_H * NFEAT) : nullptr,
            has_fin ? (cnts_base + (size_t)b_fin * NV_
                       + (size_t)hz_fin * NV_H) : nullptr,
            (s == 0) ? shape_tail : nullptr);
    }
}